// round 1
// baseline (speedup 1.0000x reference)
#include <cuda_runtime.h>
#include <math.h>

#define FULL 0xffffffffu

// Problem constants (fixed by the dataset)
#define MAXN 50000
#define MAXE 400000

// Scratch (no allocation allowed in kernel_launch)
__device__ float f_buf[MAXN * 128];   // per-node lin1 features: [f0(32) | f1x(32) | f1y(32) | f1z(32)]
__device__ float n_buf[MAXN * 256];   // per-node accum: [n0a(32) | n0b(32) | n1x(64) | n1y(64) | n1z(64)]

__host__ __device__ __forceinline__ int divup(int a, int b) { return (a + b - 1) / b; }

// ---------------------------------------------------------------------------
// Kernel 1: node pre-pass. One warp per node.
//   sc  = self-connection -> written to d_out (node part), final kernel adds alpha*conv
//   f   = lin1 features   -> f_buf (component-major)
//   also zeroes n_buf row for this node.
// ---------------------------------------------------------------------------
__global__ __launch_bounds__(256) void node_pre_kernel(
    const float* __restrict__ node_input,
    const float* __restrict__ node_attr,
    const float* __restrict__ w_sc0,
    const float* __restrict__ w_sc1,
    const float* __restrict__ w_l0,
    const float* __restrict__ w_l1,
    float* __restrict__ out_node,
    int N)
{
    __shared__ float s0[1024], s1[1024], s2[1024], s3[1024];
    for (int i = threadIdx.x; i < 1024; i += blockDim.x) {
        s0[i] = w_sc0[i]; s1[i] = w_sc1[i]; s2[i] = w_l0[i]; s3[i] = w_l1[i];
    }
    __syncthreads();

    int node = (blockIdx.x * blockDim.x + threadIdx.x) >> 5;
    int lane = threadIdx.x & 31;
    if (node >= N) return;

    const float* row = node_input + (size_t)node * 128;
    float x0  = row[lane];
    float x1a = row[32 + 3 * lane];
    float x1b = row[33 + 3 * lane];
    float x1c = row[34 + 3 * lane];
    float a = node_attr[node];

    float sc0 = 0.f, f0 = 0.f;
    float sc1x = 0.f, sc1y = 0.f, sc1z = 0.f;
    float f1x = 0.f, f1y = 0.f, f1z = 0.f;

#pragma unroll
    for (int u = 0; u < 32; u++) {
        float b0 = __shfl_sync(FULL, x0, u);
        float ba = __shfl_sync(FULL, x1a, u);
        float bb = __shfl_sync(FULL, x1b, u);
        float bc = __shfl_sync(FULL, x1c, u);
        float wsc0 = s0[u * 32 + lane];
        float wsc1 = s1[u * 32 + lane];
        float wl0  = s2[u * 32 + lane];
        float wl1  = s3[u * 32 + lane];
        sc0  += b0 * wsc0;  f0  += b0 * wl0;
        sc1x += ba * wsc1;  sc1y += bb * wsc1;  sc1z += bc * wsc1;
        f1x  += ba * wl1;   f1y  += bb * wl1;   f1z  += bc * wl1;
    }

    const float s_in = 0.17677669529663687f; // 1/sqrt(32)
    float sA = a * s_in;

    // node_self into d_out (reference layout: [sc0(32) | (w,m)->32+3w+m])
    float* on = out_node + (size_t)node * 128;
    on[lane]            = sc0 * sA;
    on[32 + 3 * lane]   = sc1x * sA;
    on[33 + 3 * lane]   = sc1y * sA;
    on[34 + 3 * lane]   = sc1z * sA;

    // f_buf (component-major for coalesced edge gathers)
    float* fb = f_buf + (size_t)node * 128;
    fb[lane]      = f0  * sA;
    fb[32 + lane] = f1x * sA;
    fb[64 + lane] = f1y * sA;
    fb[96 + lane] = f1z * sA;

    // zero accumulator row
    float4* nb = (float4*)(n_buf + (size_t)node * 256);
    nb[lane]      = make_float4(0.f, 0.f, 0.f, 0.f);
    nb[lane + 32] = make_float4(0.f, 0.f, 0.f, 0.f);
}

// ---------------------------------------------------------------------------
// Kernel 2: edge pass. One warp per edge; lane = channel (0..31).
// ---------------------------------------------------------------------------
__global__ __launch_bounds__(256) void edge_kernel(
    const int*   __restrict__ edge_src,
    const int*   __restrict__ edge_dst,
    const float* __restrict__ edge_attr,
    const float* __restrict__ edge_scalars,
    const float* __restrict__ fc_w1,
    const float* __restrict__ fc_w2,
    const float* __restrict__ w_se0a,
    const float* __restrict__ w_se0b,
    const float* __restrict__ w_se1a,
    const float* __restrict__ w_se1b,
    float* __restrict__ out_edge,
    int E)
{
    __shared__ float sw1[16 * 64];
    __shared__ float sw2[64 * 128];
    __shared__ float se0a[64], se0b[64], se1a[64], se1b[64];

    for (int i = threadIdx.x; i < 16 * 64; i += blockDim.x) sw1[i] = fc_w1[i];
    for (int i = threadIdx.x; i < 64 * 128; i += blockDim.x) sw2[i] = fc_w2[i];
    for (int i = threadIdx.x; i < 64; i += blockDim.x) {
        se0a[i] = w_se0a[i]; se0b[i] = w_se0b[i];
        se1a[i] = w_se1a[i]; se1b[i] = w_se1b[i];
    }
    __syncthreads();

    int e = (blockIdx.x * blockDim.x + threadIdx.x) >> 5;
    int lane = threadIdx.x & 31;
    if (e >= E) return;

    int src = edge_src[e];
    int dst = edge_dst[e];
    float4 ea = ((const float4*)edge_attr)[e];
    float ea0 = ea.x, e1x = ea.y, e1y = ea.z, e1z = ea.w;

    // h = sin(es @ fc_w1 / 4): lane computes cols lane and lane+32
    float es = (lane < 16) ? edge_scalars[(size_t)e * 16 + lane] : 0.f;
    float h0 = 0.f, h1 = 0.f;
#pragma unroll
    for (int k = 0; k < 16; k++) {
        float ek = __shfl_sync(FULL, es, k);
        h0 += ek * sw1[k * 64 + lane];
        h1 += ek * sw1[k * 64 + 32 + lane];
    }
    h0 = sinf(h0 * 0.25f);
    h1 = sinf(h1 * 0.25f);

    // w = h @ fc_w2 / 8: lane holds channels wA..wD
    float wA = 0.f, wB = 0.f, wC = 0.f, wD = 0.f;
#pragma unroll
    for (int j = 0; j < 32; j++) {
        float hj = __shfl_sync(FULL, h0, j);
        const float* r = sw2 + j * 128;
        wA += hj * r[lane];
        wB += hj * r[32 + lane];
        wC += hj * r[64 + lane];
        wD += hj * r[96 + lane];
    }
#pragma unroll
    for (int j = 0; j < 32; j++) {
        float hj = __shfl_sync(FULL, h1, j);
        const float* r = sw2 + (j + 32) * 128;
        wA += hj * r[lane];
        wB += hj * r[32 + lane];
        wC += hj * r[64 + lane];
        wD += hj * r[96 + lane];
    }
    wA *= 0.125f; wB *= 0.125f; wC *= 0.125f; wD *= 0.125f;

    // gather f[src] (component-major, coalesced)
    const float* fr = f_buf + (size_t)src * 128;
    float g0  = fr[lane];
    float g1x = fr[32 + lane];
    float g1y = fr[64 + lane];
    float g1z = fr[96 + lane];

    const float INV_SQRT3 = 0.5773502691896258f;

    float mA = wA * g0 * ea0;
    float dg = g1x * e1x + g1y * e1y + g1z * e1z;
    float mD = wD * dg * INV_SQRT3;
    float mBx = wB * g0 * e1x, mBy = wB * g0 * e1y, mBz = wB * g0 * e1z;
    float mCx = wC * g1x * ea0, mCy = wC * g1y * ea0, mCz = wC * g1z * ea0;

    // scatter into node accumulator (layout: n0a | n0b | n1x(64) | n1y(64) | n1z(64))
    float* nb = n_buf + (size_t)dst * 256;
    atomicAdd(nb + lane,            mA);
    atomicAdd(nb + 32 + lane,       mD);
    atomicAdd(nb + 64 + lane,       mBx);
    atomicAdd(nb + 64 + 32 + lane,  mCx);
    atomicAdd(nb + 128 + lane,      mBy);
    atomicAdd(nb + 128 + 32 + lane, mCy);
    atomicAdd(nb + 192 + lane,      mBz);
    atomicAdd(nb + 192 + 32 + lane, mCz);

    // edge outputs (se0, se1) via warp reductions
    float mBdot = mBx * e1x + mBy * e1y + mBz * e1z;
    float mCdot = mCx * e1x + mCy * e1y + mCz * e1z;

    float rA = mA * se0a[lane] + mD * se0a[32 + lane];
    float rB = mBdot * se0b[lane] + mCdot * se0b[32 + lane];
    float rC = mA * se1a[lane] + mD * se1a[32 + lane];
    float rDx = mBx * se1b[lane] + mCx * se1b[32 + lane];
    float rDy = mBy * se1b[lane] + mCy * se1b[32 + lane];
    float rDz = mBz * se1b[lane] + mCz * se1b[32 + lane];

#pragma unroll
    for (int off = 16; off > 0; off >>= 1) {
        rA  += __shfl_xor_sync(FULL, rA,  off);
        rB  += __shfl_xor_sync(FULL, rB,  off);
        rC  += __shfl_xor_sync(FULL, rC,  off);
        rDx += __shfl_xor_sync(FULL, rDx, off);
        rDy += __shfl_xor_sync(FULL, rDy, off);
        rDz += __shfl_xor_sync(FULL, rDz, off);
    }

    if (lane == 0) {
        const float s_se  = 0.08838834764831845f;  // 1/sqrt(128)
        const float inv_nn = 0.35355339059327373f; // 1/sqrt(8)
        float se0  = (rA * ea0 + rB * INV_SQRT3) * s_se;
        float se1x = (rC * e1x + rDx * ea0) * s_se;
        float se1y = (rC * e1y + rDy * ea0) * s_se;
        float se1z = (rC * e1z + rDz * ea0) * s_se;
        float4 o;
        o.x = ea0 + se0 * inv_nn;
        o.y = e1x + se1x * inv_nn;
        o.z = e1y + se1y * inv_nn;
        o.w = e1z + se1z * inv_nn;
        ((float4*)out_edge)[e] = o;
    }
}

// ---------------------------------------------------------------------------
// Kernel 3: node post-pass. One warp per node, lane = output channel w.
// ---------------------------------------------------------------------------
__global__ __launch_bounds__(256) void node_post_kernel(
    const float* __restrict__ node_attr,
    const float* __restrict__ w20,
    const float* __restrict__ w21,
    const float* __restrict__ w_alpha,
    float* __restrict__ out_node,
    int N)
{
    __shared__ float s20[2048], s21[2048], sal[64];
    for (int i = threadIdx.x; i < 2048; i += blockDim.x) { s20[i] = w20[i]; s21[i] = w21[i]; }
    for (int i = threadIdx.x; i < 64; i += blockDim.x) sal[i] = w_alpha[i];
    __syncthreads();

    int node = (blockIdx.x * blockDim.x + threadIdx.x) >> 5;
    int lane = threadIdx.x & 31;
    if (node >= N) return;

    const float inv_nn = 0.35355339059327373f;
    const float* nb = n_buf + (size_t)node * 256;
    float n0a = nb[lane] * inv_nn;
    float n0b = nb[32 + lane] * inv_nn;
    float n1ax = nb[64 + lane] * inv_nn,      n1bx = nb[64 + 32 + lane] * inv_nn;
    float n1ay = nb[128 + lane] * inv_nn,     n1by = nb[128 + 32 + lane] * inv_nn;
    float n1az = nb[192 + lane] * inv_nn,     n1bz = nb[192 + 32 + lane] * inv_nn;

    float o0 = 0.f, o1x = 0.f, o1y = 0.f, o1z = 0.f, al = 0.f;

#pragma unroll
    for (int u = 0; u < 32; u++) {
        float b  = __shfl_sync(FULL, n0a, u);
        float bx = __shfl_sync(FULL, n1ax, u);
        float by = __shfl_sync(FULL, n1ay, u);
        float bz = __shfl_sync(FULL, n1az, u);
        float wa = s20[u * 32 + lane];
        float wb = s21[u * 32 + lane];
        o0 += b * wa;
        o1x += bx * wb; o1y += by * wb; o1z += bz * wb;
        al += b * sal[u];
    }
#pragma unroll
    for (int u = 0; u < 32; u++) {
        float b  = __shfl_sync(FULL, n0b, u);
        float bx = __shfl_sync(FULL, n1bx, u);
        float by = __shfl_sync(FULL, n1by, u);
        float bz = __shfl_sync(FULL, n1bz, u);
        float wa = s20[(u + 32) * 32 + lane];
        float wb = s21[(u + 32) * 32 + lane];
        o0 += b * wa;
        o1x += bx * wb; o1y += by * wb; o1z += bz * wb;
        al += b * sal[u + 32];
    }

    float a = node_attr[node];
    const float s_mid = 0.125f; // 1/sqrt(64)
    float sc = a * s_mid;
    o0 *= sc; o1x *= sc; o1y *= sc; o1z *= sc;
    float alpha = al * sc;

    float* on = out_node + (size_t)node * 128;
    on[lane]          += alpha * o0;
    on[32 + 3 * lane] += alpha * o1x;
    on[33 + 3 * lane] += alpha * o1y;
    on[34 + 3 * lane] += alpha * o1z;
}

// ---------------------------------------------------------------------------
extern "C" void kernel_launch(void* const* d_in, const int* in_sizes, int n_in,
                              void* d_out, int out_size)
{
    const float* node_input   = (const float*)d_in[0];
    const float* node_attr    = (const float*)d_in[1];
    const int*   edge_src     = (const int*)  d_in[2];
    const int*   edge_dst     = (const int*)  d_in[3];
    const float* edge_attr    = (const float*)d_in[4];
    const float* edge_scalars = (const float*)d_in[5];
    const float* w_sc0        = (const float*)d_in[6];
    const float* w_sc1        = (const float*)d_in[7];
    const float* w_lin1_0     = (const float*)d_in[8];
    const float* w_lin1_1     = (const float*)d_in[9];
    const float* fc_w1        = (const float*)d_in[10];
    const float* fc_w2        = (const float*)d_in[11];
    const float* w_lin2_0     = (const float*)d_in[12];
    const float* w_lin2_1     = (const float*)d_in[13];
    const float* w_alpha      = (const float*)d_in[14];
    const float* w_se0a       = (const float*)d_in[15];
    const float* w_se0b       = (const float*)d_in[16];
    const float* w_se1a       = (const float*)d_in[17];
    const float* w_se1b       = (const float*)d_in[18];

    int N = in_sizes[0] / 128;
    int E = in_sizes[2];

    float* out_node = (float*)d_out;
    float* out_edge = (float*)d_out + (size_t)N * 128;

    // 8 warps (8 nodes/edges) per 256-thread block
    node_pre_kernel<<<divup(N, 8), 256>>>(node_input, node_attr,
                                          w_sc0, w_sc1, w_lin1_0, w_lin1_1,
                                          out_node, N);

    edge_kernel<<<divup(E, 8), 256>>>(edge_src, edge_dst, edge_attr, edge_scalars,
                                      fc_w1, fc_w2,
                                      w_se0a, w_se0b, w_se1a, w_se1b,
                                      out_edge, E);

    node_post_kernel<<<divup(N, 8), 256>>>(node_attr, w_lin2_0, w_lin2_1, w_alpha,
                                           out_node, N);
}

// round 2
// speedup vs baseline: 2.3347x; 2.3347x over previous
#include <cuda_runtime.h>
#include <math.h>

#define FULL 0xffffffffu
#define MAXN 50000

// Scratch (device globals; no allocation allowed)
__device__ float  f_buf[MAXN * 128];      // per-node lin1 features [f0|f1x|f1y|f1z]
__device__ float4 n_buf4[MAXN * 64];      // per-node accum: [node][u][8] = (mA,mD,mBx,mCx,mBy,mCy,mBz,mCz)

__host__ __device__ __forceinline__ int divup(int a, int b) { return (a + b - 1) / b; }

static __device__ __forceinline__ void red_v4(float* p, float a, float b, float c, float d) {
    asm volatile("red.global.add.v4.f32 [%0], {%1,%2,%3,%4};"
                 :: "l"(p), "f"(a), "f"(b), "f"(c), "f"(d) : "memory");
}
static __device__ __forceinline__ unsigned long long pack2(float lo, float hi) {
    unsigned long long r;
    asm("mov.b64 %0, {%1,%2};" : "=l"(r) : "f"(lo), "f"(hi));
    return r;
}
static __device__ __forceinline__ void fma2(unsigned long long& acc, unsigned long long a, unsigned long long b) {
    asm("fma.rn.f32x2 %0, %1, %2, %0;" : "+l"(acc) : "l"(a), "l"(b));
}
static __device__ __forceinline__ float2 unpack2(unsigned long long v) {
    float2 r;
    asm("mov.b64 {%0,%1}, %2;" : "=f"(r.x), "=f"(r.y) : "l"(v));
    return r;
}

// ---------------------------------------------------------------------------
// Kernel 1: node pre-pass. One warp per 2 nodes.
// ---------------------------------------------------------------------------
__global__ __launch_bounds__(256) void node_pre_kernel(
    const float* __restrict__ node_input,
    const float* __restrict__ node_attr,
    const float* __restrict__ w_sc0,
    const float* __restrict__ w_sc1,
    const float* __restrict__ w_l0,
    const float* __restrict__ w_l1,
    float* __restrict__ out_node,
    int N)
{
    __shared__ float s0[1024], s1[1024], s2[1024], s3[1024];
    for (int i = threadIdx.x; i < 1024; i += blockDim.x) {
        s0[i] = w_sc0[i]; s1[i] = w_sc1[i]; s2[i] = w_l0[i]; s3[i] = w_l1[i];
    }
    __syncthreads();

    int warp = (blockIdx.x * blockDim.x + threadIdx.x) >> 5;
    int lane = threadIdx.x & 31;
    int nA = warp * 2;
    int nB = nA + 1;
    if (nA >= N) return;
    bool hasB = (nB < N);

    const float* rowA = node_input + (size_t)nA * 128;
    float xA0  = rowA[lane];
    float xA1a = rowA[32 + 3 * lane];
    float xA1b = rowA[33 + 3 * lane];
    float xA1c = rowA[34 + 3 * lane];
    float aA = node_attr[nA];

    float xB0 = 0.f, xB1a = 0.f, xB1b = 0.f, xB1c = 0.f, aB = 0.f;
    if (hasB) {
        const float* rowB = node_input + (size_t)nB * 128;
        xB0  = rowB[lane];
        xB1a = rowB[32 + 3 * lane];
        xB1b = rowB[33 + 3 * lane];
        xB1c = rowB[34 + 3 * lane];
        aB = node_attr[nB];
    }

    float scA0 = 0.f, fA0 = 0.f, scA1x = 0.f, scA1y = 0.f, scA1z = 0.f, fA1x = 0.f, fA1y = 0.f, fA1z = 0.f;
    float scB0 = 0.f, fB0 = 0.f, scB1x = 0.f, scB1y = 0.f, scB1z = 0.f, fB1x = 0.f, fB1y = 0.f, fB1z = 0.f;

#pragma unroll
    for (int u = 0; u < 32; u++) {
        float wsc0 = s0[u * 32 + lane];
        float wsc1 = s1[u * 32 + lane];
        float wl0  = s2[u * 32 + lane];
        float wl1  = s3[u * 32 + lane];

        float b0 = __shfl_sync(FULL, xA0, u);
        float ba = __shfl_sync(FULL, xA1a, u);
        float bb = __shfl_sync(FULL, xA1b, u);
        float bc = __shfl_sync(FULL, xA1c, u);
        scA0  += b0 * wsc0;  fA0  += b0 * wl0;
        scA1x += ba * wsc1;  scA1y += bb * wsc1;  scA1z += bc * wsc1;
        fA1x  += ba * wl1;   fA1y  += bb * wl1;   fA1z  += bc * wl1;

        float c0 = __shfl_sync(FULL, xB0, u);
        float ca = __shfl_sync(FULL, xB1a, u);
        float cb = __shfl_sync(FULL, xB1b, u);
        float cc = __shfl_sync(FULL, xB1c, u);
        scB0  += c0 * wsc0;  fB0  += c0 * wl0;
        scB1x += ca * wsc1;  scB1y += cb * wsc1;  scB1z += cc * wsc1;
        fB1x  += ca * wl1;   fB1y  += cb * wl1;   fB1z  += cc * wl1;
    }

    const float s_in = 0.17677669529663687f; // 1/sqrt(32)
    float4 z = make_float4(0.f, 0.f, 0.f, 0.f);

    {
        float sA = aA * s_in;
        float* on = out_node + (size_t)nA * 128;
        on[lane]          = scA0 * sA;
        on[32 + 3 * lane] = scA1x * sA;
        on[33 + 3 * lane] = scA1y * sA;
        on[34 + 3 * lane] = scA1z * sA;
        float* fb = f_buf + (size_t)nA * 128;
        fb[lane]      = fA0  * sA;
        fb[32 + lane] = fA1x * sA;
        fb[64 + lane] = fA1y * sA;
        fb[96 + lane] = fA1z * sA;
        float4* nb = n_buf4 + (size_t)nA * 64;
        nb[lane * 2]     = z;
        nb[lane * 2 + 1] = z;
    }
    if (hasB) {
        float sB = aB * s_in;
        float* on = out_node + (size_t)nB * 128;
        on[lane]          = scB0 * sB;
        on[32 + 3 * lane] = scB1x * sB;
        on[33 + 3 * lane] = scB1y * sB;
        on[34 + 3 * lane] = scB1z * sB;
        float* fb = f_buf + (size_t)nB * 128;
        fb[lane]      = fB0  * sB;
        fb[32 + lane] = fB1x * sB;
        fb[64 + lane] = fB1y * sB;
        fb[96 + lane] = fB1z * sB;
        float4* nb = n_buf4 + (size_t)nB * 64;
        nb[lane * 2]     = z;
        nb[lane * 2 + 1] = z;
    }
}

// ---------------------------------------------------------------------------
// Kernel 2 (fused): per block of 128 edges:
//   GEMM1: H(128x64) = sin( ES(128x16) @ W1(16x64) * 0.25 )
//   GEMM2: W(128x128) = H @ W2(64x128) * 0.125      (f32x2 packed FMA)
//   then message construction + vector atomic scatter + edge outputs.
// Dynamic smem union: phase A = W1|EST|H|W2 (79104 B), phase B = W tile (66560 B)
// ---------------------------------------------------------------------------
#define EPAD 132
#define SWS  130

__global__ void __launch_bounds__(256, 2) edge_fused_kernel(
    const int*   __restrict__ edge_src,
    const int*   __restrict__ edge_dst,
    const float* __restrict__ edge_attr,
    const float* __restrict__ edge_scalars,
    const float* __restrict__ fc_w1,
    const float* __restrict__ fc_w2,
    const float* __restrict__ w_se0a,
    const float* __restrict__ w_se0b,
    const float* __restrict__ w_se1a,
    const float* __restrict__ w_se1b,
    float* __restrict__ out_edge,
    int E)
{
    extern __shared__ float sm[];
    float* sW1  = sm;                        // 16*64   = 1024
    float* sEST = sm + 1024;                 // 16*132  = 2112  (k-major ES^T)
    float* sH   = sm + 1024 + 2112;          // 64*132  = 8448  (k-major H)
    float* sW2  = sm + 1024 + 2112 + 8448;   // 64*128  = 8192
    float* sW   = sm;                        // phase B: 128*130 = 16640

    int t = threadIdx.x;
    int e0 = blockIdx.x * 128;

    // ---- stage weights + ES tile ----
    {
        float4 v = ((const float4*)fc_w1)[t];
        v.x *= 0.25f; v.y *= 0.25f; v.z *= 0.25f; v.w *= 0.25f;
        ((float4*)sW1)[t] = v;
    }
#pragma unroll
    for (int r = 0; r < 8; r++) {
        float4 v = ((const float4*)fc_w2)[t + r * 256];
        v.x *= 0.125f; v.y *= 0.125f; v.z *= 0.125f; v.w *= 0.125f;
        ((float4*)sW2)[t + r * 256] = v;
    }
#pragma unroll
    for (int r = 0; r < 2; r++) {
        int fidx = t + r * 256;     // 0..511 float4s of the ES tile
        int e = fidx >> 2;          // 0..127
        int k4 = fidx & 3;
        float4 v = make_float4(0.f, 0.f, 0.f, 0.f);
        if (e0 + e < E) v = ((const float4*)edge_scalars)[(size_t)(e0 + e) * 4 + k4];
        sEST[(k4 * 4 + 0) * EPAD + e] = v.x;
        sEST[(k4 * 4 + 1) * EPAD + e] = v.y;
        sEST[(k4 * 4 + 2) * EPAD + e] = v.z;
        sEST[(k4 * 4 + 3) * EPAD + e] = v.w;
    }
    __syncthreads();

    // ---- GEMM1: thread tile = 4 edges (2 pairs, 64 apart) x 8 cols ----
    {
        int txe = t & 31;   // edge pairs at txe*2 and txe*2+64
        int tyc = t >> 5;   // cols tyc*8 + j
        unsigned long long acc[8][2];
#pragma unroll
        for (int j = 0; j < 8; j++) { acc[j][0] = 0ull; acc[j][1] = 0ull; }
#pragma unroll
        for (int k = 0; k < 16; k++) {
            unsigned long long a0 = *(const unsigned long long*)(sEST + k * EPAD + txe * 2);
            unsigned long long a1 = *(const unsigned long long*)(sEST + k * EPAD + txe * 2 + 64);
#pragma unroll
            for (int j = 0; j < 8; j++) {
                float b = sW1[k * 64 + tyc * 8 + j];
                unsigned long long bb = pack2(b, b);
                fma2(acc[j][0], a0, bb);
                fma2(acc[j][1], a1, bb);
            }
        }
#pragma unroll
        for (int j = 0; j < 8; j++) {
#pragma unroll
            for (int i = 0; i < 2; i++) {
                float2 v = unpack2(acc[j][i]);
                v.x = __sinf(v.x);
                v.y = __sinf(v.y);
                *(float2*)(sH + (tyc * 8 + j) * EPAD + txe * 2 + 64 * i) = v;
            }
        }
    }
    __syncthreads();

    // ---- GEMM2: thread tile = 8 edges (4 pairs, 32 apart) x 8 outs (16 apart) ----
    {
        int tx = t & 15;    // edge pairs at tx*2 + 32*i
        int ty = t >> 4;    // outs ty + 16*j
        unsigned long long acc[8][4];
#pragma unroll
        for (int j = 0; j < 8; j++)
#pragma unroll
            for (int i = 0; i < 4; i++) acc[j][i] = 0ull;

#pragma unroll 4
        for (int k = 0; k < 64; k++) {
            unsigned long long a[4];
#pragma unroll
            for (int i = 0; i < 4; i++)
                a[i] = *(const unsigned long long*)(sH + k * EPAD + tx * 2 + 32 * i);
#pragma unroll
            for (int j = 0; j < 8; j++) {
                float b = sW2[k * 128 + ty + 16 * j];
                unsigned long long bb = pack2(b, b);
#pragma unroll
                for (int i = 0; i < 4; i++) fma2(acc[j][i], a[i], bb);
            }
        }
        __syncthreads();   // all reads of sH/sW2/sW1/sEST done before overwriting with sW
#pragma unroll
        for (int j = 0; j < 8; j++) {
#pragma unroll
            for (int i = 0; i < 4; i++) {
                float2 v = unpack2(acc[j][i]);
                int e = tx * 2 + 32 * i;
                int n = ty + 16 * j;
                sW[e * SWS + n]       = v.x;
                sW[(e + 1) * SWS + n] = v.y;
            }
        }
    }
    __syncthreads();

    // ---- message phase: warp w handles edges [w*16, w*16+16) ----
    int lane = t & 31;
    int wwid = t >> 5;

    float a0lo = w_se0a[lane],      a0hi = w_se0a[32 + lane];
    float b0lo = w_se0b[lane],      b0hi = w_se0b[32 + lane];
    float a1lo = w_se1a[lane],      a1hi = w_se1a[32 + lane];
    float b1lo = w_se1b[lane],      b1hi = w_se1b[32 + lane];

    const float INV_SQRT3 = 0.5773502691896258f;
    const float s_se   = 0.08838834764831845f;   // 1/sqrt(128)
    const float inv_nn = 0.35355339059327373f;   // 1/sqrt(8)

    for (int le = 0; le < 16; le++) {
        int e = wwid * 16 + le;
        int eg = e0 + e;
        if (eg >= E) break;

        int src = edge_src[eg];
        int dst = edge_dst[eg];
        float4 ea = ((const float4*)edge_attr)[eg];
        float ea0 = ea.x, e1x = ea.y, e1y = ea.z, e1z = ea.w;

        float wAv = sW[e * SWS + lane];
        float wBv = sW[e * SWS + 32 + lane];
        float wCv = sW[e * SWS + 64 + lane];
        float wDv = sW[e * SWS + 96 + lane];

        const float* fr = f_buf + (size_t)src * 128;
        float g0  = fr[lane];
        float g1x = fr[32 + lane];
        float g1y = fr[64 + lane];
        float g1z = fr[96 + lane];

        float mA = wAv * g0 * ea0;
        float dg = g1x * e1x + g1y * e1y + g1z * e1z;
        float mD = wDv * dg * INV_SQRT3;
        float gb = wBv * g0;
        float mBx = gb * e1x, mBy = gb * e1y, mBz = gb * e1z;
        float wCe = wCv * ea0;
        float mCx = wCe * g1x, mCy = wCe * g1y, mCz = wCe * g1z;

        float* nb = (float*)(n_buf4 + (size_t)dst * 64);
        red_v4(nb + lane * 8,     mA,  mD,  mBx, mCx);
        red_v4(nb + lane * 8 + 4, mBy, mCy, mBz, mCz);

        float mBdot = mBx * e1x + mBy * e1y + mBz * e1z;
        float mCdot = mCx * e1x + mCy * e1y + mCz * e1z;

        float rA  = mA * a0lo + mD * a0hi;
        float rB  = mBdot * b0lo + mCdot * b0hi;
        float rC  = mA * a1lo + mD * a1hi;
        float rDx = mBx * b1lo + mCx * b1hi;
        float rDy = mBy * b1lo + mCy * b1hi;
        float rDz = mBz * b1lo + mCz * b1hi;

#pragma unroll
        for (int off = 16; off > 0; off >>= 1) {
            rA  += __shfl_xor_sync(FULL, rA,  off);
            rB  += __shfl_xor_sync(FULL, rB,  off);
            rC  += __shfl_xor_sync(FULL, rC,  off);
            rDx += __shfl_xor_sync(FULL, rDx, off);
            rDy += __shfl_xor_sync(FULL, rDy, off);
            rDz += __shfl_xor_sync(FULL, rDz, off);
        }

        if (lane == 0) {
            float se0  = (rA * ea0 + rB * INV_SQRT3) * s_se;
            float se1x = (rC * e1x + rDx * ea0) * s_se;
            float se1y = (rC * e1y + rDy * ea0) * s_se;
            float se1z = (rC * e1z + rDz * ea0) * s_se;
            float4 o;
            o.x = ea0 + se0  * inv_nn;
            o.y = e1x + se1x * inv_nn;
            o.z = e1y + se1y * inv_nn;
            o.w = e1z + se1z * inv_nn;
            ((float4*)out_edge)[eg] = o;
        }
    }
}

// ---------------------------------------------------------------------------
// Kernel 3: node post-pass. One warp per 2 nodes, lane = output channel w.
// ---------------------------------------------------------------------------
__global__ __launch_bounds__(256) void node_post_kernel(
    const float* __restrict__ node_attr,
    const float* __restrict__ w20,
    const float* __restrict__ w21,
    const float* __restrict__ w_alpha,
    float* __restrict__ out_node,
    int N)
{
    __shared__ float s20[2048], s21[2048], sal[64];
    for (int i = threadIdx.x; i < 2048; i += blockDim.x) { s20[i] = w20[i]; s21[i] = w21[i]; }
    for (int i = threadIdx.x; i < 64; i += blockDim.x) sal[i] = w_alpha[i];
    __syncthreads();

    int warp = (blockIdx.x * blockDim.x + threadIdx.x) >> 5;
    int lane = threadIdx.x & 31;
    int nA = warp * 2;
    int nB = nA + 1;
    if (nA >= N) return;
    bool hasB = (nB < N);

    const float inv_nn = 0.35355339059327373f;

    float4 vA1 = n_buf4[(size_t)nA * 64 + lane * 2];
    float4 vA2 = n_buf4[(size_t)nA * 64 + lane * 2 + 1];
    float An0a = vA1.x * inv_nn, An0b = vA1.y * inv_nn;
    float An1ax = vA1.z * inv_nn, An1bx = vA1.w * inv_nn;
    float An1ay = vA2.x * inv_nn, An1by = vA2.y * inv_nn;
    float An1az = vA2.z * inv_nn, An1bz = vA2.w * inv_nn;

    float Bn0a = 0.f, Bn0b = 0.f, Bn1ax = 0.f, Bn1bx = 0.f, Bn1ay = 0.f, Bn1by = 0.f, Bn1az = 0.f, Bn1bz = 0.f;
    if (hasB) {
        float4 vB1 = n_buf4[(size_t)nB * 64 + lane * 2];
        float4 vB2 = n_buf4[(size_t)nB * 64 + lane * 2 + 1];
        Bn0a = vB1.x * inv_nn; Bn0b = vB1.y * inv_nn;
        Bn1ax = vB1.z * inv_nn; Bn1bx = vB1.w * inv_nn;
        Bn1ay = vB2.x * inv_nn; Bn1by = vB2.y * inv_nn;
        Bn1az = vB2.z * inv_nn; Bn1bz = vB2.w * inv_nn;
    }

    float Ao0 = 0.f, Ao1x = 0.f, Ao1y = 0.f, Ao1z = 0.f, Aal = 0.f;
    float Bo0 = 0.f, Bo1x = 0.f, Bo1y = 0.f, Bo1z = 0.f, Bal = 0.f;

#pragma unroll
    for (int u = 0; u < 32; u++) {
        float wa = s20[u * 32 + lane];
        float wb = s21[u * 32 + lane];
        float wal = sal[u];

        float b  = __shfl_sync(FULL, An0a, u);
        float bx = __shfl_sync(FULL, An1ax, u);
        float by = __shfl_sync(FULL, An1ay, u);
        float bz = __shfl_sync(FULL, An1az, u);
        Ao0 += b * wa; Ao1x += bx * wb; Ao1y += by * wb; Ao1z += bz * wb; Aal += b * wal;

        float c  = __shfl_sync(FULL, Bn0a, u);
        float cx = __shfl_sync(FULL, Bn1ax, u);
        float cy = __shfl_sync(FULL, Bn1ay, u);
        float cz = __shfl_sync(FULL, Bn1az, u);
        Bo0 += c * wa; Bo1x += cx * wb; Bo1y += cy * wb; Bo1z += cz * wb; Bal += c * wal;
    }
#pragma unroll
    for (int u = 0; u < 32; u++) {
        float wa = s20[(u + 32) * 32 + lane];
        float wb = s21[(u + 32) * 32 + lane];
        float wal = sal[u + 32];

        float b  = __shfl_sync(FULL, An0b, u);
        float bx = __shfl_sync(FULL, An1bx, u);
        float by = __shfl_sync(FULL, An1by, u);
        float bz = __shfl_sync(FULL, An1bz, u);
        Ao0 += b * wa; Ao1x += bx * wb; Ao1y += by * wb; Ao1z += bz * wb; Aal += b * wal;

        float c  = __shfl_sync(FULL, Bn0b, u);
        float cx = __shfl_sync(FULL, Bn1bx, u);
        float cy = __shfl_sync(FULL, Bn1by, u);
        float cz = __shfl_sync(FULL, Bn1bz, u);
        Bo0 += c * wa; Bo1x += cx * wb; Bo1y += cy * wb; Bo1z += cz * wb; Bal += c * wal;
    }

    const float s_mid = 0.125f; // 1/sqrt(64)
    {
        float sc = node_attr[nA] * s_mid;
        float alpha = Aal * sc;
        float* on = out_node + (size_t)nA * 128;
        on[lane]          += alpha * (Ao0 * sc);
        on[32 + 3 * lane] += alpha * (Ao1x * sc);
        on[33 + 3 * lane] += alpha * (Ao1y * sc);
        on[34 + 3 * lane] += alpha * (Ao1z * sc);
    }
    if (hasB) {
        float sc = node_attr[nB] * s_mid;
        float alpha = Bal * sc;
        float* on = out_node + (size_t)nB * 128;
        on[lane]          += alpha * (Bo0 * sc);
        on[32 + 3 * lane] += alpha * (Bo1x * sc);
        on[33 + 3 * lane] += alpha * (Bo1y * sc);
        on[34 + 3 * lane] += alpha * (Bo1z * sc);
    }
}

// ---------------------------------------------------------------------------
extern "C" void kernel_launch(void* const* d_in, const int* in_sizes, int n_in,
                              void* d_out, int out_size)
{
    const float* node_input   = (const float*)d_in[0];
    const float* node_attr    = (const float*)d_in[1];
    const int*   edge_src     = (const int*)  d_in[2];
    const int*   edge_dst     = (const int*)  d_in[3];
    const float* edge_attr    = (const float*)d_in[4];
    const float* edge_scalars = (const float*)d_in[5];
    const float* w_sc0        = (const float*)d_in[6];
    const float* w_sc1        = (const float*)d_in[7];
    const float* w_lin1_0     = (const float*)d_in[8];
    const float* w_lin1_1     = (const float*)d_in[9];
    const float* fc_w1        = (const float*)d_in[10];
    const float* fc_w2        = (const float*)d_in[11];
    const float* w_lin2_0     = (const float*)d_in[12];
    const float* w_lin2_1     = (const float*)d_in[13];
    const float* w_alpha      = (const float*)d_in[14];
    const float* w_se0a       = (const float*)d_in[15];
    const float* w_se0b       = (const float*)d_in[16];
    const float* w_se1a       = (const float*)d_in[17];
    const float* w_se1b       = (const float*)d_in[18];

    int N = in_sizes[0] / 128;
    int E = in_sizes[2];

    float* out_node = (float*)d_out;
    float* out_edge = (float*)d_out + (size_t)N * 128;

    const int SMEM_EDGE = (1024 + 2112 + 8448 + 8192) * 4; // 79104 bytes
    cudaFuncSetAttribute(edge_fused_kernel,
                         cudaFuncAttributeMaxDynamicSharedMemorySize, SMEM_EDGE);

    // 8 warps per block; 2 nodes per warp
    node_pre_kernel<<<divup(N, 16), 256>>>(node_input, node_attr,
                                           w_sc0, w_sc1, w_lin1_0, w_lin1_1,
                                           out_node, N);

    edge_fused_kernel<<<divup(E, 128), 256, SMEM_EDGE>>>(
        edge_src, edge_dst, edge_attr, edge_scalars,
        fc_w1, fc_w2, w_se0a, w_se0b, w_se1a, w_se1b,
        out_edge, E);

    node_post_kernel<<<divup(N, 16), 256>>>(node_attr, w_lin2_0, w_lin2_1, w_alpha,
                                            out_node, N);
}

// round 3
// speedup vs baseline: 2.4391x; 1.0447x over previous
#include <cuda_runtime.h>
#include <math.h>
#include <stdint.h>

#define FULL 0xffffffffu
#define MAXN 50000

// Scratch (device globals; no allocation allowed)
__device__ float  f_buf[MAXN * 128];      // per-node lin1 features [f0|f1x|f1y|f1z]
__device__ float4 n_buf4[MAXN * 64];      // per-node accum: [node][u][8] = (mA,mD,mBx,mCx,mBy,mCy,mBz,mCz)

__host__ __device__ __forceinline__ int divup(int a, int b) { return (a + b - 1) / b; }

static __device__ __forceinline__ void red_v4(float* p, float a, float b, float c, float d) {
    asm volatile("red.global.add.v4.f32 [%0], {%1,%2,%3,%4};"
                 :: "l"(p), "f"(a), "f"(b), "f"(c), "f"(d) : "memory");
}
static __device__ __forceinline__ unsigned long long pack2(float lo, float hi) {
    unsigned long long r;
    asm("mov.b64 %0, {%1,%2};" : "=l"(r) : "f"(lo), "f"(hi));
    return r;
}
static __device__ __forceinline__ void fma2(unsigned long long& acc, unsigned long long a, unsigned long long b) {
    asm("fma.rn.f32x2 %0, %1, %2, %0;" : "+l"(acc) : "l"(a), "l"(b));
}
static __device__ __forceinline__ float2 unpack2(unsigned long long v) {
    float2 r;
    asm("mov.b64 {%0,%1}, %2;" : "=f"(r.x), "=f"(r.y) : "l"(v));
    return r;
}
static __device__ __forceinline__ uint32_t to_tf32(float f) {
    uint32_t r; asm("cvt.rna.tf32.f32 %0, %1;" : "=r"(r) : "f"(f)); return r;
}

// ---------------------------------------------------------------------------
// Kernel 1: node pre-pass. One warp per 2 nodes.
// ---------------------------------------------------------------------------
__global__ __launch_bounds__(256) void node_pre_kernel(
    const float* __restrict__ node_input,
    const float* __restrict__ node_attr,
    const float* __restrict__ w_sc0,
    const float* __restrict__ w_sc1,
    const float* __restrict__ w_l0,
    const float* __restrict__ w_l1,
    float* __restrict__ out_node,
    int N)
{
    __shared__ float s0[1024], s1[1024], s2[1024], s3[1024];
    __shared__ float stage[8][132];
    for (int i = threadIdx.x; i < 1024; i += blockDim.x) {
        s0[i] = w_sc0[i]; s1[i] = w_sc1[i]; s2[i] = w_l0[i]; s3[i] = w_l1[i];
    }
    __syncthreads();

    int warp = (blockIdx.x * blockDim.x + threadIdx.x) >> 5;
    int wid  = (threadIdx.x >> 5);
    int lane = threadIdx.x & 31;
    int nA = warp * 2;
    int nB = nA + 1;
    if (nA >= N) return;
    bool hasB = (nB < N);

    const float* rowA = node_input + (size_t)nA * 128;
    float xA0  = rowA[lane];
    float xA1a = rowA[32 + 3 * lane];
    float xA1b = rowA[33 + 3 * lane];
    float xA1c = rowA[34 + 3 * lane];
    float aA = node_attr[nA];

    float xB0 = 0.f, xB1a = 0.f, xB1b = 0.f, xB1c = 0.f, aB = 0.f;
    if (hasB) {
        const float* rowB = node_input + (size_t)nB * 128;
        xB0  = rowB[lane];
        xB1a = rowB[32 + 3 * lane];
        xB1b = rowB[33 + 3 * lane];
        xB1c = rowB[34 + 3 * lane];
        aB = node_attr[nB];
    }

    float scA0 = 0.f, fA0 = 0.f, scA1x = 0.f, scA1y = 0.f, scA1z = 0.f, fA1x = 0.f, fA1y = 0.f, fA1z = 0.f;
    float scB0 = 0.f, fB0 = 0.f, scB1x = 0.f, scB1y = 0.f, scB1z = 0.f, fB1x = 0.f, fB1y = 0.f, fB1z = 0.f;

#pragma unroll
    for (int u = 0; u < 32; u++) {
        float wsc0 = s0[u * 32 + lane];
        float wsc1 = s1[u * 32 + lane];
        float wl0  = s2[u * 32 + lane];
        float wl1  = s3[u * 32 + lane];

        float b0 = __shfl_sync(FULL, xA0, u);
        float ba = __shfl_sync(FULL, xA1a, u);
        float bb = __shfl_sync(FULL, xA1b, u);
        float bc = __shfl_sync(FULL, xA1c, u);
        scA0  += b0 * wsc0;  fA0  += b0 * wl0;
        scA1x += ba * wsc1;  scA1y += bb * wsc1;  scA1z += bc * wsc1;
        fA1x  += ba * wl1;   fA1y  += bb * wl1;   fA1z  += bc * wl1;

        float c0 = __shfl_sync(FULL, xB0, u);
        float ca = __shfl_sync(FULL, xB1a, u);
        float cb = __shfl_sync(FULL, xB1b, u);
        float cc = __shfl_sync(FULL, xB1c, u);
        scB0  += c0 * wsc0;  fB0  += c0 * wl0;
        scB1x += ca * wsc1;  scB1y += cb * wsc1;  scB1z += cc * wsc1;
        fB1x  += ca * wl1;   fB1y  += cb * wl1;   fB1z  += cc * wl1;
    }

    const float s_in = 0.17677669529663687f; // 1/sqrt(32)
    float* st = stage[wid];

    {
        float sA = aA * s_in;
        st[lane]          = scA0 * sA;
        st[32 + 3 * lane] = scA1x * sA;
        st[33 + 3 * lane] = scA1y * sA;
        st[34 + 3 * lane] = scA1z * sA;
        __syncwarp();
        ((float4*)(out_node + (size_t)nA * 128))[lane] = ((const float4*)st)[lane];
        __syncwarp();
        float* fb = f_buf + (size_t)nA * 128;
        fb[lane]      = fA0  * sA;
        fb[32 + lane] = fA1x * sA;
        fb[64 + lane] = fA1y * sA;
        fb[96 + lane] = fA1z * sA;
    }
    if (hasB) {
        float sB = aB * s_in;
        st[lane]          = scB0 * sB;
        st[32 + 3 * lane] = scB1x * sB;
        st[33 + 3 * lane] = scB1y * sB;
        st[34 + 3 * lane] = scB1z * sB;
        __syncwarp();
        ((float4*)(out_node + (size_t)nB * 128))[lane] = ((const float4*)st)[lane];
        __syncwarp();
        float* fb = f_buf + (size_t)nB * 128;
        fb[lane]      = fB0  * sB;
        fb[32 + lane] = fB1x * sB;
        fb[64 + lane] = fB1y * sB;
        fb[96 + lane] = fB1z * sB;
    }
}

// ---------------------------------------------------------------------------
// Kernel 2 (fused): per block of 128 edges:
//   GEMM1: H(128x64) = sin( ES(128x16) @ W1(16x64) * 0.25 )   (f32x2 FFMA)
//   GEMM2: W(128x128) = H @ W2(64x128) * 0.125                 (tf32 mma.sync)
//   then message construction + vector atomic scatter + edge outputs.
// smem: [ sBf 8192f (tf32 B fragments) | region 17152f union:
//         phaseA = sW1(1024)+sEST(2112)+sH(8704), phaseB = sW(128x134) ]
// ---------------------------------------------------------------------------
#define EPAD 132
#define HP   68
#define SWS  134

__global__ void __launch_bounds__(256, 2) edge_fused_kernel(
    const int*   __restrict__ edge_src,
    const int*   __restrict__ edge_dst,
    const float* __restrict__ edge_attr,
    const float* __restrict__ edge_scalars,
    const float* __restrict__ fc_w1,
    const float* __restrict__ fc_w2,
    const float* __restrict__ w_se0a,
    const float* __restrict__ w_se0b,
    const float* __restrict__ w_se1a,
    const float* __restrict__ w_se1b,
    float* __restrict__ out_edge,
    int E)
{
    extern __shared__ float sm[];
    float* sBf    = sm;                  // 8192: B fragments (tf32 bits)
    float* region = sm + 8192;
    float* sW1  = region;                // 1024
    float* sEST = region + 1024;         // 16*132 = 2112 (k-major ES^T)
    float* sH   = region + 3136;         // 128*68 = 8704 (edge-major, tf32 bits)
    float* sW   = region;                // phase B: 128*134 = 17152

    int t = threadIdx.x;
    int e0 = blockIdx.x * 128;
    int lane = t & 31;
    int wwid = t >> 5;

    // ---- stage W1 (scaled), ES tile, and B fragments (tf32, scaled) ----
    {
        float4 v = ((const float4*)fc_w1)[t];
        v.x *= 0.25f; v.y *= 0.25f; v.z *= 0.25f; v.w *= 0.25f;
        ((float4*)sW1)[t] = v;
    }
#pragma unroll
    for (int r = 0; r < 2; r++) {
        int fidx = t + r * 256;     // 0..511 float4s of the ES tile
        int e = fidx >> 2;          // 0..127
        int k4 = fidx & 3;
        float4 v = make_float4(0.f, 0.f, 0.f, 0.f);
        if (e0 + e < E) v = ((const float4*)edge_scalars)[(size_t)(e0 + e) * 4 + k4];
        sEST[(k4 * 4 + 0) * EPAD + e] = v.x;
        sEST[(k4 * 4 + 1) * EPAD + e] = v.y;
        sEST[(k4 * 4 + 2) * EPAD + e] = v.z;
        sEST[(k4 * 4 + 3) * EPAD + e] = v.w;
    }
    {
        uint32_t* sBfu = (uint32_t*)sBf;
#pragma unroll
        for (int rep = 0; rep < 32; rep++) {
            int idx = rep * 256 + t;        // 0..8191, coalesced gmem reads
            int n = idx & 127;
            int k = idx >> 7;
            float val = fc_w2[k * 128 + n] * 0.125f;
            int nt = n >> 3, ks = k >> 3, rb = (k >> 2) & 1;
            int ln = ((n & 7) << 2) | (k & 3);
            sBfu[(nt * 8 + ks) * 64 + ln * 2 + rb] = to_tf32(val);
        }
    }
    __syncthreads();

    // ---- GEMM1: thread tile = 4 edges (2 pairs, 64 apart) x 8 cols ----
    {
        int txe = t & 31;   // edge pairs at txe*2 and txe*2+64
        int tyc = t >> 5;   // cols tyc*8 + j
        unsigned long long acc[8][2];
#pragma unroll
        for (int j = 0; j < 8; j++) { acc[j][0] = 0ull; acc[j][1] = 0ull; }
#pragma unroll
        for (int k = 0; k < 16; k++) {
            unsigned long long a0 = *(const unsigned long long*)(sEST + k * EPAD + txe * 2);
            unsigned long long a1 = *(const unsigned long long*)(sEST + k * EPAD + txe * 2 + 64);
#pragma unroll
            for (int j = 0; j < 8; j++) {
                float b = sW1[k * 64 + tyc * 8 + j];
                unsigned long long bb = pack2(b, b);
                fma2(acc[j][0], a0, bb);
                fma2(acc[j][1], a1, bb);
            }
        }
        uint32_t* sHu = (uint32_t*)sH;
#pragma unroll
        for (int j = 0; j < 8; j++) {
            int col = tyc * 8 + j;
#pragma unroll
            for (int i = 0; i < 2; i++) {
                float2 v = unpack2(acc[j][i]);
                int e = txe * 2 + 64 * i;
                sHu[e * HP + col]       = to_tf32(__sinf(v.x));
                sHu[(e + 1) * HP + col] = to_tf32(__sinf(v.y));
            }
        }
    }
    __syncthreads();

    // ---- load A fragments (16 edges per warp, K=64 -> 8 ksteps) ----
    uint32_t afr[8][4];
    {
        const uint32_t* sHu = (const uint32_t*)sH;
        int er = wwid * 16 + (lane >> 2);
        int kl = lane & 3;
#pragma unroll
        for (int ks = 0; ks < 8; ks++) {
            int k0 = ks * 8 + kl;
            afr[ks][0] = sHu[er * HP + k0];
            afr[ks][1] = sHu[(er + 8) * HP + k0];
            afr[ks][2] = sHu[er * HP + k0 + 4];
            afr[ks][3] = sHu[(er + 8) * HP + k0 + 4];
        }
    }
    __syncthreads();   // sH dead; region becomes sW

    // ---- GEMM2: tf32 mma, warp computes 16 edges x 128 outs ----
    {
        const uint32_t* bf = (const uint32_t*)sBf;
        int er = wwid * 16 + (lane >> 2);
        int nb = (lane & 3) * 2;
#pragma unroll
        for (int nt = 0; nt < 16; nt++) {
            float c0 = 0.f, c1 = 0.f, c2 = 0.f, c3 = 0.f;
#pragma unroll
            for (int ks = 0; ks < 8; ks++) {
                uint2 b = *(const uint2*)(bf + (nt * 8 + ks) * 64 + lane * 2);
                asm volatile(
                    "mma.sync.aligned.m16n8k8.row.col.f32.tf32.tf32.f32 "
                    "{%0,%1,%2,%3},{%4,%5,%6,%7},{%8,%9},{%0,%1,%2,%3};"
                    : "+f"(c0), "+f"(c1), "+f"(c2), "+f"(c3)
                    : "r"(afr[ks][0]), "r"(afr[ks][1]), "r"(afr[ks][2]), "r"(afr[ks][3]),
                      "r"(b.x), "r"(b.y));
            }
            int n = nt * 8 + nb;
            *(float2*)(sW + er * SWS + n)       = make_float2(c0, c1);
            *(float2*)(sW + (er + 8) * SWS + n) = make_float2(c2, c3);
        }
    }
    __syncthreads();

    // ---- message phase: warp w handles edges [w*16, w*16+16) ----
    float a0lo = w_se0a[lane],      a0hi = w_se0a[32 + lane];
    float b0lo = w_se0b[lane],      b0hi = w_se0b[32 + lane];
    float a1lo = w_se1a[lane],      a1hi = w_se1a[32 + lane];
    float b1lo = w_se1b[lane],      b1hi = w_se1b[32 + lane];

    const float INV_SQRT3 = 0.5773502691896258f;
    const float s_se   = 0.08838834764831845f;   // 1/sqrt(128)
    const float inv_nn = 0.35355339059327373f;   // 1/sqrt(8)

    for (int le = 0; le < 16; le++) {
        int e = wwid * 16 + le;
        int eg = e0 + e;
        if (eg >= E) break;

        int src = edge_src[eg];
        int dst = edge_dst[eg];
        float4 ea = ((const float4*)edge_attr)[eg];
        float ea0 = ea.x, e1x = ea.y, e1y = ea.z, e1z = ea.w;

        float wAv = sW[e * SWS + lane];
        float wBv = sW[e * SWS + 32 + lane];
        float wCv = sW[e * SWS + 64 + lane];
        float wDv = sW[e * SWS + 96 + lane];

        const float* fr = f_buf + (size_t)src * 128;
        float g0  = fr[lane];
        float g1x = fr[32 + lane];
        float g1y = fr[64 + lane];
        float g1z = fr[96 + lane];

        float mA = wAv * g0 * ea0;
        float dg = g1x * e1x + g1y * e1y + g1z * e1z;
        float mD = wDv * dg * INV_SQRT3;
        float gb = wBv * g0;
        float mBx = gb * e1x, mBy = gb * e1y, mBz = gb * e1z;
        float wCe = wCv * ea0;
        float mCx = wCe * g1x, mCy = wCe * g1y, mCz = wCe * g1z;

        float* nb = (float*)(n_buf4 + (size_t)dst * 64);
        red_v4(nb + lane * 8,     mA,  mD,  mBx, mCx);
        red_v4(nb + lane * 8 + 4, mBy, mCy, mBz, mCz);

        float mBdot = mBx * e1x + mBy * e1y + mBz * e1z;
        float mCdot = mCx * e1x + mCy * e1y + mCz * e1z;

        float rA  = mA * a0lo + mD * a0hi;
        float rB  = mBdot * b0lo + mCdot * b0hi;
        float rC  = mA * a1lo + mD * a1hi;
        float rDx = mBx * b1lo + mCx * b1hi;
        float rDy = mBy * b1lo + mCy * b1hi;
        float rDz = mBz * b1lo + mCz * b1hi;

#pragma unroll
        for (int off = 16; off > 0; off >>= 1) {
            rA  += __shfl_xor_sync(FULL, rA,  off);
            rB  += __shfl_xor_sync(FULL, rB,  off);
            rC  += __shfl_xor_sync(FULL, rC,  off);
            rDx += __shfl_xor_sync(FULL, rDx, off);
            rDy += __shfl_xor_sync(FULL, rDy, off);
            rDz += __shfl_xor_sync(FULL, rDz, off);
        }

        if (lane == 0) {
            float se0  = (rA * ea0 + rB * INV_SQRT3) * s_se;
            float se1x = (rC * e1x + rDx * ea0) * s_se;
            float se1y = (rC * e1y + rDy * ea0) * s_se;
            float se1z = (rC * e1z + rDz * ea0) * s_se;
            float4 o;
            o.x = ea0 + se0  * inv_nn;
            o.y = e1x + se1x * inv_nn;
            o.z = e1y + se1y * inv_nn;
            o.w = e1z + se1z * inv_nn;
            ((float4*)out_edge)[eg] = o;
        }
    }
}

// ---------------------------------------------------------------------------
// Kernel 3: node post-pass. One warp per 2 nodes, lane = output channel w.
// ---------------------------------------------------------------------------
__global__ __launch_bounds__(256) void node_post_kernel(
    const float* __restrict__ node_attr,
    const float* __restrict__ w20,
    const float* __restrict__ w21,
    const float* __restrict__ w_alpha,
    float* __restrict__ out_node,
    int N)
{
    __shared__ float s20[2048], s21[2048], sal[64];
    __shared__ float stage[8][132];
    for (int i = threadIdx.x; i < 2048; i += blockDim.x) { s20[i] = w20[i]; s21[i] = w21[i]; }
    for (int i = threadIdx.x; i < 64; i += blockDim.x) sal[i] = w_alpha[i];
    __syncthreads();

    int warp = (blockIdx.x * blockDim.x + threadIdx.x) >> 5;
    int wid  = (threadIdx.x >> 5);
    int lane = threadIdx.x & 31;
    int nA = warp * 2;
    int nB = nA + 1;
    if (nA >= N) return;
    bool hasB = (nB < N);

    const float inv_nn = 0.35355339059327373f;

    float4 vA1 = n_buf4[(size_t)nA * 64 + lane * 2];
    float4 vA2 = n_buf4[(size_t)nA * 64 + lane * 2 + 1];
    float An0a = vA1.x * inv_nn, An0b = vA1.y * inv_nn;
    float An1ax = vA1.z * inv_nn, An1bx = vA1.w * inv_nn;
    float An1ay = vA2.x * inv_nn, An1by = vA2.y * inv_nn;
    float An1az = vA2.z * inv_nn, An1bz = vA2.w * inv_nn;

    float Bn0a = 0.f, Bn0b = 0.f, Bn1ax = 0.f, Bn1bx = 0.f, Bn1ay = 0.f, Bn1by = 0.f, Bn1az = 0.f, Bn1bz = 0.f;
    if (hasB) {
        float4 vB1 = n_buf4[(size_t)nB * 64 + lane * 2];
        float4 vB2 = n_buf4[(size_t)nB * 64 + lane * 2 + 1];
        Bn0a = vB1.x * inv_nn; Bn0b = vB1.y * inv_nn;
        Bn1ax = vB1.z * inv_nn; Bn1bx = vB1.w * inv_nn;
        Bn1ay = vB2.x * inv_nn; Bn1by = vB2.y * inv_nn;
        Bn1az = vB2.z * inv_nn; Bn1bz = vB2.w * inv_nn;
    }

    float Ao0 = 0.f, Ao1x = 0.f, Ao1y = 0.f, Ao1z = 0.f, Aal = 0.f;
    float Bo0 = 0.f, Bo1x = 0.f, Bo1y = 0.f, Bo1z = 0.f, Bal = 0.f;

#pragma unroll
    for (int u = 0; u < 32; u++) {
        float wa = s20[u * 32 + lane];
        float wb = s21[u * 32 + lane];
        float wal = sal[u];

        float b  = __shfl_sync(FULL, An0a, u);
        float bx = __shfl_sync(FULL, An1ax, u);
        float by = __shfl_sync(FULL, An1ay, u);
        float bz = __shfl_sync(FULL, An1az, u);
        Ao0 += b * wa; Ao1x += bx * wb; Ao1y += by * wb; Ao1z += bz * wb; Aal += b * wal;

        float c  = __shfl_sync(FULL, Bn0a, u);
        float cx = __shfl_sync(FULL, Bn1ax, u);
        float cy = __shfl_sync(FULL, Bn1ay, u);
        float cz = __shfl_sync(FULL, Bn1az, u);
        Bo0 += c * wa; Bo1x += cx * wb; Bo1y += cy * wb; Bo1z += cz * wb; Bal += c * wal;
    }
#pragma unroll
    for (int u = 0; u < 32; u++) {
        float wa = s20[(u + 32) * 32 + lane];
        float wb = s21[(u + 32) * 32 + lane];
        float wal = sal[u + 32];

        float b  = __shfl_sync(FULL, An0b, u);
        float bx = __shfl_sync(FULL, An1bx, u);
        float by = __shfl_sync(FULL, An1by, u);
        float bz = __shfl_sync(FULL, An1bz, u);
        Ao0 += b * wa; Ao1x += bx * wb; Ao1y += by * wb; Ao1z += bz * wb; Aal += b * wal;

        float c  = __shfl_sync(FULL, Bn0b, u);
        float cx = __shfl_sync(FULL, Bn1bx, u);
        float cy = __shfl_sync(FULL, Bn1by, u);
        float cz = __shfl_sync(FULL, Bn1bz, u);
        Bo0 += c * wa; Bo1x += cx * wb; Bo1y += cy * wb; Bo1z += cz * wb; Bal += c * wal;
    }

    const float s_mid = 0.125f; // 1/sqrt(64)
    float* st = stage[wid];
    {
        float sc = node_attr[nA] * s_mid;
        float alpha = Aal * sc;
        float as = alpha * sc;
        st[lane]          = as * Ao0;
        st[32 + 3 * lane] = as * Ao1x;
        st[33 + 3 * lane] = as * Ao1y;
        st[34 + 3 * lane] = as * Ao1z;
        __syncwarp();
        float4* on4 = (float4*)(out_node + (size_t)nA * 128);
        float4 cur = on4[lane];
        float4 add = ((const float4*)st)[lane];
        cur.x += add.x; cur.y += add.y; cur.z += add.z; cur.w += add.w;
        on4[lane] = cur;
        __syncwarp();
    }
    if (hasB) {
        float sc = node_attr[nB] * s_mid;
        float alpha = Bal * sc;
        float as = alpha * sc;
        st[lane]          = as * Bo0;
        st[32 + 3 * lane] = as * Bo1x;
        st[33 + 3 * lane] = as * Bo1y;
        st[34 + 3 * lane] = as * Bo1z;
        __syncwarp();
        float4* on4 = (float4*)(out_node + (size_t)nB * 128);
        float4 cur = on4[lane];
        float4 add = ((const float4*)st)[lane];
        cur.x += add.x; cur.y += add.y; cur.z += add.z; cur.w += add.w;
        on4[lane] = cur;
    }
}

// ---------------------------------------------------------------------------
extern "C" void kernel_launch(void* const* d_in, const int* in_sizes, int n_in,
                              void* d_out, int out_size)
{
    const float* node_input   = (const float*)d_in[0];
    const float* node_attr    = (const float*)d_in[1];
    const int*   edge_src     = (const int*)  d_in[2];
    const int*   edge_dst     = (const int*)  d_in[3];
    const float* edge_attr    = (const float*)d_in[4];
    const float* edge_scalars = (const float*)d_in[5];
    const float* w_sc0        = (const float*)d_in[6];
    const float* w_sc1        = (const float*)d_in[7];
    const float* w_lin1_0     = (const float*)d_in[8];
    const float* w_lin1_1     = (const float*)d_in[9];
    const float* fc_w1        = (const float*)d_in[10];
    const float* fc_w2        = (const float*)d_in[11];
    const float* w_lin2_0     = (const float*)d_in[12];
    const float* w_lin2_1     = (const float*)d_in[13];
    const float* w_alpha      = (const float*)d_in[14];
    const float* w_se0a       = (const float*)d_in[15];
    const float* w_se0b       = (const float*)d_in[16];
    const float* w_se1a       = (const float*)d_in[17];
    const float* w_se1b       = (const float*)d_in[18];

    int N = in_sizes[0] / 128;
    int E = in_sizes[2];

    float* out_node = (float*)d_out;
    float* out_edge = (float*)d_out + (size_t)N * 128;

    // zero the accumulator via a captured memset node
    void* nbuf_ptr = nullptr;
    cudaGetSymbolAddress(&nbuf_ptr, n_buf4);
    cudaMemsetAsync(nbuf_ptr, 0, (size_t)N * 64 * sizeof(float4));

    const int SMEM_EDGE = (8192 + 17152) * 4; // 101376 bytes
    cudaFuncSetAttribute(edge_fused_kernel,
                         cudaFuncAttributeMaxDynamicSharedMemorySize, SMEM_EDGE);

    node_pre_kernel<<<divup(N, 16), 256>>>(node_input, node_attr,
                                           w_sc0, w_sc1, w_lin1_0, w_lin1_1,
                                           out_node, N);

    edge_fused_kernel<<<divup(E, 128), 256, SMEM_EDGE>>>(
        edge_src, edge_dst, edge_attr, edge_scalars,
        fc_w1, fc_w2, w_se0a, w_se0b, w_se1a, w_se1b,
        out_edge, E);

    node_post_kernel<<<divup(N, 16), 256>>>(node_attr, w_lin2_0, w_lin2_1, w_alpha,
                                            out_node, N);
}

// round 5
// speedup vs baseline: 3.0252x; 1.2403x over previous
#include <cuda_runtime.h>
#include <math.h>
#include <stdint.h>

#define FULL 0xffffffffu
#define MAXN 50000

// Scratch (device globals; no allocation allowed)
__device__ float  f_buf[MAXN * 128];      // per-node lin1 features [f0|f1x|f1y|f1z]
// per-node accum: [node][ A-part: u*4 -> (mA,mD,mBx,mCx) | B-part: u*4 -> (mBy,mCy,mBz,mCz) ]
__device__ float4 n_buf4[MAXN * 64];

__host__ __device__ __forceinline__ int divup(int a, int b) { return (a + b - 1) / b; }

static __device__ __forceinline__ void red_v4(float* p, float a, float b, float c, float d) {
    asm volatile("red.global.add.v4.f32 [%0], {%1,%2,%3,%4};"
                 :: "l"(p), "f"(a), "f"(b), "f"(c), "f"(d) : "memory");
}
static __device__ __forceinline__ unsigned long long pack2(float lo, float hi) {
    unsigned long long r;
    asm("mov.b64 %0, {%1,%2};" : "=l"(r) : "f"(lo), "f"(hi));
    return r;
}
static __device__ __forceinline__ void fma2(unsigned long long& acc, unsigned long long a, unsigned long long b) {
    asm("fma.rn.f32x2 %0, %1, %2, %0;" : "+l"(acc) : "l"(a), "l"(b));
}
static __device__ __forceinline__ float2 unpack2(unsigned long long v) {
    float2 r;
    asm("mov.b64 {%0,%1}, %2;" : "=f"(r.x), "=f"(r.y) : "l"(v));
    return r;
}
static __device__ __forceinline__ uint32_t to_tf32(float f) {
    uint32_t r; asm("cvt.rna.tf32.f32 %0, %1;" : "=r"(r) : "f"(f)); return r;
}

// ---------------------------------------------------------------------------
// Kernel 1: node pre-pass. One warp per 2 nodes; x broadcast via smem v4.
// ---------------------------------------------------------------------------
__global__ __launch_bounds__(256) void node_pre_kernel(
    const float* __restrict__ node_input,
    const float* __restrict__ node_attr,
    const float* __restrict__ w_sc0,
    const float* __restrict__ w_sc1,
    const float* __restrict__ w_l0,
    const float* __restrict__ w_l1,
    float* __restrict__ out_node,
    int N)
{
    __shared__ float s0[1024], s1[1024], s2[1024], s3[1024];
    __shared__ float4 sx[8][2][32];
    for (int i = threadIdx.x; i < 1024; i += blockDim.x) {
        s0[i] = w_sc0[i]; s1[i] = w_sc1[i]; s2[i] = w_l0[i]; s3[i] = w_l1[i];
    }
    __syncthreads();

    int warp = (blockIdx.x * blockDim.x + threadIdx.x) >> 5;
    int wid  = (threadIdx.x >> 5);
    int lane = threadIdx.x & 31;
    int nA = warp * 2;
    int nB = nA + 1;
    if (nA >= N) return;
    bool hasB = (nB < N);

    {
        const float* rowA = node_input + (size_t)nA * 128;
        sx[wid][0][lane] = make_float4(rowA[lane], rowA[32 + 3 * lane],
                                       rowA[33 + 3 * lane], rowA[34 + 3 * lane]);
        if (hasB) {
            const float* rowB = node_input + (size_t)nB * 128;
            sx[wid][1][lane] = make_float4(rowB[lane], rowB[32 + 3 * lane],
                                           rowB[33 + 3 * lane], rowB[34 + 3 * lane]);
        }
    }
    float aA = node_attr[nA];
    float aB = hasB ? node_attr[nB] : 0.f;
    __syncwarp();

    float scA0 = 0.f, fA0 = 0.f, scA1x = 0.f, scA1y = 0.f, scA1z = 0.f, fA1x = 0.f, fA1y = 0.f, fA1z = 0.f;
    float scB0 = 0.f, fB0 = 0.f, scB1x = 0.f, scB1y = 0.f, scB1z = 0.f, fB1x = 0.f, fB1y = 0.f, fB1z = 0.f;

#pragma unroll
    for (int u = 0; u < 32; u++) {
        float wsc0 = s0[u * 32 + lane];
        float wsc1 = s1[u * 32 + lane];
        float wl0  = s2[u * 32 + lane];
        float wl1  = s3[u * 32 + lane];

        float4 xa = sx[wid][0][u];  // LDS.128 broadcast
        scA0  += xa.x * wsc0;  fA0  += xa.x * wl0;
        scA1x += xa.y * wsc1;  scA1y += xa.z * wsc1;  scA1z += xa.w * wsc1;
        fA1x  += xa.y * wl1;   fA1y  += xa.z * wl1;   fA1z  += xa.w * wl1;

        float4 xb = sx[wid][1][u];
        scB0  += xb.x * wsc0;  fB0  += xb.x * wl0;
        scB1x += xb.y * wsc1;  scB1y += xb.z * wsc1;  scB1z += xb.w * wsc1;
        fB1x  += xb.y * wl1;   fB1y  += xb.z * wl1;   fB1z  += xb.w * wl1;
    }
    __syncwarp();

    const float s_in = 0.17677669529663687f; // 1/sqrt(32)
    float* st = (float*)&sx[wid][0][0];

    {
        float sA = aA * s_in;
        st[lane]          = scA0 * sA;
        st[32 + 3 * lane] = scA1x * sA;
        st[33 + 3 * lane] = scA1y * sA;
        st[34 + 3 * lane] = scA1z * sA;
        __syncwarp();
        ((float4*)(out_node + (size_t)nA * 128))[lane] = ((const float4*)st)[lane];
        __syncwarp();
        float* fb = f_buf + (size_t)nA * 128;
        fb[lane]      = fA0  * sA;
        fb[32 + lane] = fA1x * sA;
        fb[64 + lane] = fA1y * sA;
        fb[96 + lane] = fA1z * sA;
    }
    if (hasB) {
        float sB = aB * s_in;
        st[lane]          = scB0 * sB;
        st[32 + 3 * lane] = scB1x * sB;
        st[33 + 3 * lane] = scB1y * sB;
        st[34 + 3 * lane] = scB1z * sB;
        __syncwarp();
        ((float4*)(out_node + (size_t)nB * 128))[lane] = ((const float4*)st)[lane];
        __syncwarp();
        float* fb = f_buf + (size_t)nB * 128;
        fb[lane]      = fB0  * sB;
        fb[32 + lane] = fB1x * sB;
        fb[64 + lane] = fB1y * sB;
        fb[96 + lane] = fB1z * sB;
    }
}

// ---------------------------------------------------------------------------
// Kernel 2 (fused): per block of 128 edges:
//   GEMM1: H(128x64) = sin( ES(128x16) @ W1(16x64) * 0.25 )   (f32x2 FFMA)
//   GEMM2: W(128x128) = H @ W2(64x128) * 0.125                 (tf32 mma.sync)
//   then batched message construction + vector atomic scatter + edge outputs.
// ---------------------------------------------------------------------------
#define EPAD 132
#define HP   68
#define SWS  134

__global__ void __launch_bounds__(256, 2) edge_fused_kernel(
    const int*   __restrict__ edge_src,
    const int*   __restrict__ edge_dst,
    const float* __restrict__ edge_attr,
    const float* __restrict__ edge_scalars,
    const float* __restrict__ fc_w1,
    const float* __restrict__ fc_w2,
    const float* __restrict__ w_se0a,
    const float* __restrict__ w_se0b,
    const float* __restrict__ w_se1a,
    const float* __restrict__ w_se1b,
    float* __restrict__ out_edge,
    int E)
{
    extern __shared__ float sm[];
    float* sBf    = sm;                  // 8192: B fragments (tf32 bits)
    float* region = sm + 8192;
    float* sW1  = region;                // 1024
    float* sEST = region + 1024;         // 16*132 = 2112 (k-major ES^T)
    float* sH   = region + 3136;         // 128*68 = 8704 (edge-major, tf32 bits)
    float* sW   = region;                // phase B: 128*134 = 17152

    int t = threadIdx.x;
    int e0 = blockIdx.x * 128;
    int lane = t & 31;
    int wwid = t >> 5;

    // ---- stage W1 (scaled), ES tile, and B fragments (tf32, scaled) ----
    {
        float4 v = ((const float4*)fc_w1)[t];
        v.x *= 0.25f; v.y *= 0.25f; v.z *= 0.25f; v.w *= 0.25f;
        ((float4*)sW1)[t] = v;
    }
#pragma unroll
    for (int r = 0; r < 2; r++) {
        int fidx = t + r * 256;     // 0..511 float4s of the ES tile
        int e = fidx >> 2;          // 0..127
        int k4 = fidx & 3;
        float4 v = make_float4(0.f, 0.f, 0.f, 0.f);
        if (e0 + e < E) v = ((const float4*)edge_scalars)[(size_t)(e0 + e) * 4 + k4];
        sEST[(k4 * 4 + 0) * EPAD + e] = v.x;
        sEST[(k4 * 4 + 1) * EPAD + e] = v.y;
        sEST[(k4 * 4 + 2) * EPAD + e] = v.z;
        sEST[(k4 * 4 + 3) * EPAD + e] = v.w;
    }
    {
        uint32_t* sBfu = (uint32_t*)sBf;
#pragma unroll
        for (int rep = 0; rep < 32; rep++) {
            int idx = rep * 256 + t;        // 0..8191, coalesced gmem reads
            int n = idx & 127;
            int k = idx >> 7;
            float val = fc_w2[k * 128 + n] * 0.125f;
            int nt = n >> 3, ks = k >> 3, rb = (k >> 2) & 1;
            int ln = ((n & 7) << 2) | (k & 3);
            sBfu[(nt * 8 + ks) * 64 + ln * 2 + rb] = to_tf32(val);
        }
    }
    __syncthreads();

    // ---- GEMM1: thread tile = 4 edges (2 pairs, 64 apart) x 8 cols ----
    {
        int txe = t & 31;   // edge pairs at txe*2 and txe*2+64
        int tyc = t >> 5;   // cols tyc*8 + j
        unsigned long long acc[8][2];
#pragma unroll
        for (int j = 0; j < 8; j++) { acc[j][0] = 0ull; acc[j][1] = 0ull; }
#pragma unroll
        for (int k = 0; k < 16; k++) {
            unsigned long long a0 = *(const unsigned long long*)(sEST + k * EPAD + txe * 2);
            unsigned long long a1 = *(const unsigned long long*)(sEST + k * EPAD + txe * 2 + 64);
#pragma unroll
            for (int j = 0; j < 8; j++) {
                float b = sW1[k * 64 + tyc * 8 + j];
                unsigned long long bb = pack2(b, b);
                fma2(acc[j][0], a0, bb);
                fma2(acc[j][1], a1, bb);
            }
        }
        uint32_t* sHu = (uint32_t*)sH;
#pragma unroll
        for (int j = 0; j < 8; j++) {
            int col = tyc * 8 + j;
#pragma unroll
            for (int i = 0; i < 2; i++) {
                float2 v = unpack2(acc[j][i]);
                int e = txe * 2 + 64 * i;
                sHu[e * HP + col]       = to_tf32(__sinf(v.x));
                sHu[(e + 1) * HP + col] = to_tf32(__sinf(v.y));
            }
        }
    }
    __syncthreads();

    // ---- load A fragments (16 edges per warp, K=64 -> 8 ksteps) ----
    uint32_t afr[8][4];
    {
        const uint32_t* sHu = (const uint32_t*)sH;
        int er = wwid * 16 + (lane >> 2);
        int kl = lane & 3;
#pragma unroll
        for (int ks = 0; ks < 8; ks++) {
            int k0 = ks * 8 + kl;
            afr[ks][0] = sHu[er * HP + k0];
            afr[ks][1] = sHu[(er + 8) * HP + k0];
            afr[ks][2] = sHu[er * HP + k0 + 4];
            afr[ks][3] = sHu[(er + 8) * HP + k0 + 4];
        }
    }
    __syncthreads();   // sH dead; region becomes sW

    // ---- GEMM2: tf32 mma, warp computes 16 edges x 128 outs ----
    {
        const uint32_t* bf = (const uint32_t*)sBf;
        int er = wwid * 16 + (lane >> 2);
        int nb = (lane & 3) * 2;
#pragma unroll
        for (int nt = 0; nt < 16; nt++) {
            float c0 = 0.f, c1 = 0.f, c2 = 0.f, c3 = 0.f;
#pragma unroll
            for (int ks = 0; ks < 8; ks++) {
                uint2 b = *(const uint2*)(bf + (nt * 8 + ks) * 64 + lane * 2);
                asm volatile(
                    "mma.sync.aligned.m16n8k8.row.col.f32.tf32.tf32.f32 "
                    "{%0,%1,%2,%3},{%4,%5,%6,%7},{%8,%9},{%0,%1,%2,%3};"
                    : "+f"(c0), "+f"(c1), "+f"(c2), "+f"(c3)
                    : "r"(afr[ks][0]), "r"(afr[ks][1]), "r"(afr[ks][2]), "r"(afr[ks][3]),
                      "r"(b.x), "r"(b.y));
            }
            int n = nt * 8 + nb;
            *(float2*)(sW + er * SWS + n)       = make_float2(c0, c1);
            *(float2*)(sW + (er + 8) * SWS + n) = make_float2(c2, c3);
        }
    }
    __syncthreads();

    // ---- message phase: warp handles edges [base, base+16), batched by 4 ----
    float a0lo = w_se0a[lane],      a0hi = w_se0a[32 + lane];
    float b0lo = w_se0b[lane],      b0hi = w_se0b[32 + lane];
    float a1lo = w_se1a[lane],      a1hi = w_se1a[32 + lane];
    float b1lo = w_se1b[lane],      b1hi = w_se1b[32 + lane];

    const float INV_SQRT3 = 0.5773502691896258f;
    const float s_se   = 0.08838834764831845f;   // 1/sqrt(128)
    const float inv_nn = 0.35355339059327373f;   // 1/sqrt(8)

    int base = e0 + wwid * 16;

    if (base + 16 <= E) {
        // fast path, no bounds checks
#pragma unroll 1
        for (int g = 0; g < 4; g++) {
            int   dstv[4];
            float4 eav[4];
            float g0v[4], g1xv[4], g1yv[4], g1zv[4];
            float wAv[4], wBv[4], wCv[4], wDv[4];
#pragma unroll
            for (int i = 0; i < 4; i++) {
                int eg = base + g * 4 + i;
                int el = wwid * 16 + g * 4 + i;
                int src = edge_src[eg];
                dstv[i] = edge_dst[eg];
                eav[i] = ((const float4*)edge_attr)[eg];
                const float* fr = f_buf + (size_t)src * 128;
                g0v[i]  = fr[lane];
                g1xv[i] = fr[32 + lane];
                g1yv[i] = fr[64 + lane];
                g1zv[i] = fr[96 + lane];
                const float* wr = sW + el * SWS;
                wAv[i] = wr[lane];
                wBv[i] = wr[32 + lane];
                wCv[i] = wr[64 + lane];
                wDv[i] = wr[96 + lane];
            }
#pragma unroll
            for (int i = 0; i < 4; i++) {
                float ea0 = eav[i].x, e1x = eav[i].y, e1y = eav[i].z, e1z = eav[i].w;

                float mA = wAv[i] * g0v[i] * ea0;
                float dg = g1xv[i] * e1x + g1yv[i] * e1y + g1zv[i] * e1z;
                float mD = wDv[i] * dg * INV_SQRT3;
                float gb = wBv[i] * g0v[i];
                float mBx = gb * e1x, mBy = gb * e1y, mBz = gb * e1z;
                float wCe = wCv[i] * ea0;
                float mCx = wCe * g1xv[i], mCy = wCe * g1yv[i], mCz = wCe * g1zv[i];

                float* nb = (float*)(n_buf4 + (size_t)dstv[i] * 64);
                red_v4(nb + lane * 4,       mA,  mD,  mBx, mCx);
                red_v4(nb + 128 + lane * 4, mBy, mCy, mBz, mCz);

                float mBdot = mBx * e1x + mBy * e1y + mBz * e1z;
                float mCdot = mCx * e1x + mCy * e1y + mCz * e1z;

                float rA  = mA * a0lo + mD * a0hi;
                float rB  = mBdot * b0lo + mCdot * b0hi;
                float rC  = mA * a1lo + mD * a1hi;
                float rDx = mBx * b1lo + mCx * b1hi;
                float rDy = mBy * b1lo + mCy * b1hi;
                float rDz = mBz * b1lo + mCz * b1hi;

#pragma unroll
                for (int off = 16; off > 0; off >>= 1) {
                    rA  += __shfl_xor_sync(FULL, rA,  off);
                    rB  += __shfl_xor_sync(FULL, rB,  off);
                    rC  += __shfl_xor_sync(FULL, rC,  off);
                    rDx += __shfl_xor_sync(FULL, rDx, off);
                    rDy += __shfl_xor_sync(FULL, rDy, off);
                    rDz += __shfl_xor_sync(FULL, rDz, off);
                }

                if (lane == 0) {
                    float se0  = (rA * ea0 + rB * INV_SQRT3) * s_se;
                    float se1x = (rC * e1x + rDx * ea0) * s_se;
                    float se1y = (rC * e1y + rDy * ea0) * s_se;
                    float se1z = (rC * e1z + rDz * ea0) * s_se;
                    float4 o;
                    o.x = ea0 + se0  * inv_nn;
                    o.y = e1x + se1x * inv_nn;
                    o.z = e1y + se1y * inv_nn;
                    o.w = e1z + se1z * inv_nn;
                    ((float4*)out_edge)[base + g * 4 + i] = o;
                }
            }
        }
    } else {
        // guarded tail path
        for (int le = 0; le < 16; le++) {
            int eg = base + le;
            if (eg >= E) break;
            int el = wwid * 16 + le;

            int src = edge_src[eg];
            int dst = edge_dst[eg];
            float4 ea = ((const float4*)edge_attr)[eg];
            float ea0 = ea.x, e1x = ea.y, e1y = ea.z, e1z = ea.w;

            const float* wr = sW + el * SWS;
            float wAs = wr[lane];
            float wBs = wr[32 + lane];
            float wCs = wr[64 + lane];
            float wDs = wr[96 + lane];

            const float* fr = f_buf + (size_t)src * 128;
            float g0  = fr[lane];
            float g1x = fr[32 + lane];
            float g1y = fr[64 + lane];
            float g1z = fr[96 + lane];

            float mA = wAs * g0 * ea0;
            float dg = g1x * e1x + g1y * e1y + g1z * e1z;
            float mD = wDs * dg * INV_SQRT3;
            float gb = wBs * g0;
            float mBx = gb * e1x, mBy = gb * e1y, mBz = gb * e1z;
            float wCe = wCs * ea0;
            float mCx = wCe * g1x, mCy = wCe * g1y, mCz = wCe * g1z;

            float* nb = (float*)(n_buf4 + (size_t)dst * 64);
            red_v4(nb + lane * 4,       mA,  mD,  mBx, mCx);
            red_v4(nb + 128 + lane * 4, mBy, mCy, mBz, mCz);

            float mBdot = mBx * e1x + mBy * e1y + mBz * e1z;
            float mCdot = mCx * e1x + mCy * e1y + mCz * e1z;

            float rA  = mA * a0lo + mD * a0hi;
            float rB  = mBdot * b0lo + mCdot * b0hi;
            float rC  = mA * a1lo + mD * a1hi;
            float rDx = mBx * b1lo + mCx * b1hi;
            float rDy = mBy * b1lo + mCy * b1hi;
            float rDz = mBz * b1lo + mCz * b1hi;

#pragma unroll
            for (int off = 16; off > 0; off >>= 1) {
                rA  += __shfl_xor_sync(FULL, rA,  off);
                rB  += __shfl_xor_sync(FULL, rB,  off);
                rC  += __shfl_xor_sync(FULL, rC,  off);
                rDx += __shfl_xor_sync(FULL, rDx, off);
                rDy += __shfl_xor_sync(FULL, rDy, off);
                rDz += __shfl_xor_sync(FULL, rDz, off);
            }

            if (lane == 0) {
                float se0  = (rA * ea0 + rB * INV_SQRT3) * s_se;
                float se1x = (rC * e1x + rDx * ea0) * s_se;
                float se1y = (rC * e1y + rDy * ea0) * s_se;
                float se1z = (rC * e1z + rDz * ea0) * s_se;
                float4 o;
                o.x = ea0 + se0  * inv_nn;
                o.y = e1x + se1x * inv_nn;
                o.z = e1y + se1y * inv_nn;
                o.w = e1z + se1z * inv_nn;
                ((float4*)out_edge)[eg] = o;
            }
        }
    }
}

// ---------------------------------------------------------------------------
// Kernel 3: node post-pass. One warp per 2 nodes; n broadcast via smem v4.
// ---------------------------------------------------------------------------
__global__ __launch_bounds__(256) void node_post_kernel(
    const float* __restrict__ node_attr,
    const float* __restrict__ w20,
    const float* __restrict__ w21,
    const float* __restrict__ w_alpha,
    float* __restrict__ out_node,
    int N)
{
    __shared__ float s20[2048], s21[2048], sal[64];
    __shared__ float4 sx[8][2][2][32];   // [wid][node][half][u]
    for (int i = threadIdx.x; i < 2048; i += blockDim.x) { s20[i] = w20[i]; s21[i] = w21[i]; }
    for (int i = threadIdx.x; i < 64; i += blockDim.x) sal[i] = w_alpha[i];
    __syncthreads();

    int warp = (blockIdx.x * blockDim.x + threadIdx.x) >> 5;
    int wid  = (threadIdx.x >> 5);
    int lane = threadIdx.x & 31;
    int nA = warp * 2;
    int nB = nA + 1;
    if (nA >= N) return;
    bool hasB = (nB < N);

    {
        float4 vA1 = n_buf4[(size_t)nA * 64 + lane];        // (mA,mD,mBx,mCx) sums
        float4 vA2 = n_buf4[(size_t)nA * 64 + 32 + lane];   // (mBy,mCy,mBz,mCz) sums
        sx[wid][0][0][lane] = make_float4(vA1.x, vA1.z, vA2.x, vA2.z); // n0a,n1ax,n1ay,n1az
        sx[wid][0][1][lane] = make_float4(vA1.y, vA1.w, vA2.y, vA2.w); // n0b,n1bx,n1by,n1bz
        if (hasB) {
            float4 vB1 = n_buf4[(size_t)nB * 64 + lane];
            float4 vB2 = n_buf4[(size_t)nB * 64 + 32 + lane];
            sx[wid][1][0][lane] = make_float4(vB1.x, vB1.z, vB2.x, vB2.z);
            sx[wid][1][1][lane] = make_float4(vB1.y, vB1.w, vB2.y, vB2.w);
        }
    }
    __syncwarp();

    float Ao0 = 0.f, Ao1x = 0.f, Ao1y = 0.f, Ao1z = 0.f, Aal = 0.f;
    float Bo0 = 0.f, Bo1x = 0.f, Bo1y = 0.f, Bo1z = 0.f, Bal = 0.f;

#pragma unroll
    for (int u = 0; u < 32; u++) {
        float wa = s20[u * 32 + lane];
        float wb = s21[u * 32 + lane];
        float wal = sal[u];

        float4 xa = sx[wid][0][0][u];
        Ao0 += xa.x * wa; Ao1x += xa.y * wb; Ao1y += xa.z * wb; Ao1z += xa.w * wb; Aal += xa.x * wal;
        float4 xb = sx[wid][1][0][u];
        Bo0 += xb.x * wa; Bo1x += xb.y * wb; Bo1y += xb.z * wb; Bo1z += xb.w * wb; Bal += xb.x * wal;
    }
#pragma unroll
    for (int u = 0; u < 32; u++) {
        float wa = s20[(u + 32) * 32 + lane];
        float wb = s21[(u + 32) * 32 + lane];
        float wal = sal[u + 32];

        float4 xa = sx[wid][0][1][u];
        Ao0 += xa.x * wa; Ao1x += xa.y * wb; Ao1y += xa.z * wb; Ao1z += xa.w * wb; Aal += xa.x * wal;
        float4 xb = sx[wid][1][1][u];
        Bo0 += xb.x * wa; Bo1x += xb.y * wb; Bo1y += xb.z * wb; Bo1z += xb.w * wb; Bal += xb.x * wal;
    }
    __syncwarp();

    const float s_mid  = 0.125f;                 // 1/sqrt(64)
    const float inv_nn = 0.35355339059327373f;   // 1/sqrt(8)
    float* st = (float*)&sx[wid][0][0][0];
    {
        float sc = node_attr[nA] * s_mid * inv_nn;   // one inv_nn per n-factor
        float k = (Aal * sc) * sc;                   // alpha * scale
        st[lane]          = k * Ao0;
        st[32 + 3 * lane] = k * Ao1x;
        st[33 + 3 * lane] = k * Ao1y;
        st[34 + 3 * lane] = k * Ao1z;
        __syncwarp();
        float4* on4 = (float4*)(out_node + (size_t)nA * 128);
        float4 cur = on4[lane];
        float4 add = ((const float4*)st)[lane];
        cur.x += add.x; cur.y += add.y; cur.z += add.z; cur.w += add.w;
        on4[lane] = cur;
        __syncwarp();
    }
    if (hasB) {
        float sc = node_attr[nB] * s_mid * inv_nn;
        float k = (Bal * sc) * sc;
        st[lane]          = k * Bo0;
        st[32 + 3 * lane] = k * Bo1x;
        st[33 + 3 * lane] = k * Bo1y;
        st[34 + 3 * lane] = k * Bo1z;
        __syncwarp();
        float4* on4 = (float4*)(out_node + (size_t)nB * 128);
        float4 cur = on4[lane];
        float4 add = ((const float4*)st)[lane];
        cur.x += add.x; cur.y += add.y; cur.z += add.z; cur.w += add.w;
        on4[lane] = cur;
    }
}

// ---------------------------------------------------------------------------
extern "C" void kernel_launch(void* const* d_in, const int* in_sizes, int n_in,
                              void* d_out, int out_size)
{
    const float* node_input   = (const float*)d_in[0];
    const float* node_attr    = (const float*)d_in[1];
    const int*   edge_src     = (const int*)  d_in[2];
    const int*   edge_dst     = (const int*)  d_in[3];
    const float* edge_attr    = (const float*)d_in[4];
    const float* edge_scalars = (const float*)d_in[5];
    const float* w_sc0        = (const float*)d_in[6];
    const float* w_sc1        = (const float*)d_in[7];
    const float* w_lin1_0     = (const float*)d_in[8];
    const float* w_lin1_1     = (const float*)d_in[9];
    const float* fc_w1        = (const float*)d_in[10];
    const float* fc_w2        = (const float*)d_in[11];
    const float* w_lin2_0     = (const float*)d_in[12];
    const float* w_lin2_1     = (const float*)d_in[13];
    const float* w_alpha      = (const float*)d_in[14];
    const float* w_se0a       = (const float*)d_in[15];
    const float* w_se0b       = (const float*)d_in[16];
    const float* w_se1a       = (const float*)d_in[17];
    const float* w_se1b       = (const float*)d_in[18];

    int N = in_sizes[0] / 128;
    int E = in_sizes[2];

    float* out_node = (float*)d_out;
    float* out_edge = (float*)d_out + (size_t)N * 128;

    // zero the accumulator via a captured memset node
    void* nbuf_ptr = nullptr;
    cudaGetSymbolAddress(&nbuf_ptr, n_buf4);
    cudaMemsetAsync(nbuf_ptr, 0, (size_t)N * 64 * sizeof(float4));

    const int SMEM_EDGE = (8192 + 17152) * 4; // 101376 bytes
    cudaFuncSetAttribute(edge_fused_kernel,
                         cudaFuncAttributeMaxDynamicSharedMemorySize, SMEM_EDGE);

    node_pre_kernel<<<divup(N, 16), 256>>>(node_input, node_attr,
                                           w_sc0, w_sc1, w_lin1_0, w_lin1_1,
                                           out_node, N);

    edge_fused_kernel<<<divup(E, 128), 256, SMEM_EDGE>>>(
        edge_src, edge_dst, edge_attr, edge_scalars,
        fc_w1, fc_w2, w_se0a, w_se0b, w_se1a, w_se1b,
        out_edge, E);

    node_post_kernel<<<divup(N, 16), 256>>>(node_attr, w_lin2_0, w_lin2_1, w_alpha,
                                            out_node, N);
}